// round 1
// baseline (speedup 1.0000x reference)
#include <cuda_runtime.h>

#define B_  512
#define T_  1024
#define D_  128
#define H_  256
#define G_  1024   // 4*H
#define K1  384    // D + H
#define K2  512    // 2H
#define BM  32     // batch tile
#define BJ  32     // hidden tile
#define BN  128    // 4 * BJ gate columns
#define BK  64
#define NCTA 128   // 16 M-tiles * 8 J-tiles
#define NTHREADS 256

// Persistent state (double-buffered h, single-buffered c)
__device__ float g_h1[2][B_ * H_];
__device__ float g_c1[B_ * H_];
__device__ float g_h2[2][B_ * H_];
__device__ float g_c2[B_ * H_];

// Grid barrier state (sense-reversing; returns to {0,0} after an even barrier count)
__device__ unsigned g_bar_cnt = 0;
__device__ unsigned g_bar_sense = 0;

__device__ __forceinline__ void grid_barrier(unsigned& local_sense) {
    __syncthreads();
    if (threadIdx.x == 0) {
        unsigned want = local_sense ^ 1u;
        __threadfence();
        unsigned arrived = atomicAdd(&g_bar_cnt, 1u);
        if (arrived == NCTA - 1) {
            g_bar_cnt = 0;
            __threadfence();
            atomicExch(&g_bar_sense, want);
        } else {
            volatile unsigned* s = &g_bar_sense;
            while (*s != want) { __nanosleep(64); }
            __threadfence();
        }
        local_sense = want;
    }
    __syncthreads();
}

__device__ __forceinline__ float fsig(float x)  { return 1.0f / (1.0f + __expf(-x)); }
__device__ __forceinline__ float ftanh(float x) { return 2.0f / (1.0f + __expf(-2.0f * x)) - 1.0f; }

// One LSTM layer step for this CTA's (batch-tile, hidden-tile).
// A[b][k] = (k < SPLIT) ? src0[b*stride0 + k] : src1[b*H + k - SPLIT]
// gates = A @ W + bias, columns {g*H + j0 + jj : g in 0..3, jj in 0..31}
template<int K, int SPLIT>
__device__ void lstm_phase(const float* __restrict__ src0, int stride0,
                           const float* __restrict__ src1,
                           const float* __restrict__ W,
                           const float* __restrict__ bias,
                           float* __restrict__ hout,
                           float* __restrict__ cst,
                           int bm0, int j0,
                           float* __restrict__ Ws,   // BK*BN floats (reused as gate staging)
                           float* __restrict__ As)   // BM*BK floats
{
    const int tid = threadIdx.x;
    const int tx  = tid & 31;   // 0..31 -> 4 gate columns each
    const int ty  = tid >> 5;   // 0..7  -> 4 batch rows each

    float acc[4][4] = {};

    for (int k0 = 0; k0 < K; k0 += BK) {
        // ---- load A tile: BM x BK (k-fast -> coalesced global, conflict-free STS)
        #pragma unroll
        for (int p = 0; p < (BM * BK) / NTHREADS; ++p) {   // 8
            int e = p * NTHREADS + tid;
            int m = e >> 6;       // / BK
            int k = e & (BK - 1);
            int kg = k0 + k;
            int b = bm0 + m;
            float v = (kg < SPLIT) ? src0[b * stride0 + kg]
                                   : src1[b * H_ + (kg - SPLIT)];
            As[m * BK + k] = v;
        }
        // ---- load W tile: BK rows x 128 cols (4 segments of 32 per row)
        #pragma unroll
        for (int p = 0; p < BK / 8; ++p) {                 // 8 passes, 8 rows each
            int krow = p * 8 + (tid >> 5);
            int ln4  = (tid & 31) * 4;
            int g    = ln4 >> 5;
            int jj   = ln4 & 31;
            const float4 wv = *(const float4*)&W[(size_t)(k0 + krow) * G_ + g * H_ + j0 + jj];
            *(float4*)&Ws[krow * BN + ln4] = wv;
        }
        __syncthreads();

        // ---- FMA mainloop
        #pragma unroll 16
        for (int kk = 0; kk < BK; ++kk) {
            float a0 = As[(ty * 4 + 0) * BK + kk];
            float a1 = As[(ty * 4 + 1) * BK + kk];
            float a2 = As[(ty * 4 + 2) * BK + kk];
            float a3 = As[(ty * 4 + 3) * BK + kk];
            float4 bv = *(float4*)&Ws[kk * BN + tx * 4];
            acc[0][0] += a0 * bv.x; acc[0][1] += a0 * bv.y; acc[0][2] += a0 * bv.z; acc[0][3] += a0 * bv.w;
            acc[1][0] += a1 * bv.x; acc[1][1] += a1 * bv.y; acc[1][2] += a1 * bv.z; acc[1][3] += a1 * bv.w;
            acc[2][0] += a2 * bv.x; acc[2][1] += a2 * bv.y; acc[2][2] += a2 * bv.z; acc[2][3] += a2 * bv.w;
            acc[3][0] += a3 * bv.x; acc[3][1] += a3 * bv.y; acc[3][2] += a3 * bv.z; acc[3][3] += a3 * bv.w;
        }
        __syncthreads();
    }

    // ---- stage gates (reuse Ws): layout [m][ln], ln = gate*32 + jj
    #pragma unroll
    for (int i = 0; i < 4; ++i)
        #pragma unroll
        for (int j = 0; j < 4; ++j)
            Ws[(ty * 4 + i) * BN + (tx * 4 + j)] = acc[i][j];
    __syncthreads();

    // ---- cell update: 32 m x 32 jj pairs, 4 per thread
    #pragma unroll
    for (int p = 0; p < (BM * BJ) / NTHREADS; ++p) {       // 4
        int e  = p * NTHREADS + tid;
        int m  = e >> 5;
        int jj = e & 31;
        float gf = Ws[m * BN + 0 * 32 + jj] + bias[0 * H_ + j0 + jj];
        float gi = Ws[m * BN + 1 * 32 + jj] + bias[1 * H_ + j0 + jj];
        float gg = Ws[m * BN + 2 * 32 + jj] + bias[2 * H_ + j0 + jj];
        float go = Ws[m * BN + 3 * 32 + jj] + bias[3 * H_ + j0 + jj];
        float f  = fsig(gf);
        float ii = fsig(gi);
        float g  = ftanh(gg);
        float o  = fsig(go);
        int idx  = (bm0 + m) * H_ + j0 + jj;
        float c  = f * cst[idx] + ii * g;
        cst[idx]  = c;
        hout[idx] = o * ftanh(c);
    }
    __syncthreads();   // protect Ws before next phase reuses it
}

__global__ void __launch_bounds__(NTHREADS, 1)
lstm_persistent_kernel(const float* __restrict__ x,
                       const float* __restrict__ W1, const float* __restrict__ b1,
                       const float* __restrict__ W2, const float* __restrict__ b2,
                       const float* __restrict__ Wout, const float* __restrict__ bout,
                       float* __restrict__ out)
{
    __shared__ float Ws[BK * BN];   // 32 KB
    __shared__ float As[BM * BK];   // 8 KB

    unsigned sense = 0;
    const int cta = blockIdx.x;
    const int bm0 = (cta >> 3) * BM;   // 16 batch tiles
    const int j0  = (cta & 7) * BJ;    // 8 hidden tiles

    // ---- zero all state
    {
        int gtid = cta * NTHREADS + threadIdx.x;
        int nthr = NCTA * NTHREADS;
        for (int i = gtid; i < B_ * H_; i += nthr) {
            g_h1[0][i] = 0.f; g_h1[1][i] = 0.f; g_c1[i] = 0.f;
            g_h2[0][i] = 0.f; g_h2[1][i] = 0.f; g_c2[i] = 0.f;
        }
    }
    grid_barrier(sense);               // barrier #1

    int p = 0, q = 0;
    for (int t = 0; t < T_; ++t) {
        // Layer 1: A = [x_t, h1(prev)], writes h1(cur) into other buffer
        lstm_phase<K1, D_>(x + (size_t)t * D_, T_ * D_, g_h1[p],
                           W1, b1, g_h1[p ^ 1], g_c1, bm0, j0, Ws, As);
        grid_barrier(sense);
        // Layer 2: A = [h1(cur), h2(prev)]
        lstm_phase<K2, H_>(g_h1[p ^ 1], H_, g_h2[q],
                           W2, b2, g_h2[q ^ 1], g_c2, bm0, j0, Ws, As);
        grid_barrier(sense);
        p ^= 1; q ^= 1;
    }
    // 1 + 2048 barriers so far; g_h2[q] holds the final h2.

    // ---- output projection: out[b] = h2_final[b] . Wout + bout
    {
        const float* h2f = g_h2[q];
        int gtid = cta * NTHREADS + threadIdx.x;
        if (gtid < B_) {
            float s = 0.f;
            #pragma unroll 8
            for (int k = 0; k < H_; ++k)
                s += h2f[gtid * H_ + k] * Wout[k];
            out[gtid] = s + bout[0];
        }
    }
    grid_barrier(sense);               // barrier #2050 (even -> state resets for replay)
}

extern "C" void kernel_launch(void* const* d_in, const int* in_sizes, int n_in,
                              void* d_out, int out_size)
{
    (void)in_sizes; (void)n_in; (void)out_size;
    const float* x    = (const float*)d_in[0];
    const float* W1   = (const float*)d_in[1];
    const float* b1   = (const float*)d_in[2];
    const float* W2   = (const float*)d_in[3];
    const float* b2   = (const float*)d_in[4];
    const float* Wout = (const float*)d_in[5];
    const float* bout = (const float*)d_in[6];
    lstm_persistent_kernel<<<NCTA, NTHREADS>>>(x, W1, b1, W2, b2, Wout, bout,
                                               (float*)d_out);
}